// round 1
// baseline (speedup 1.0000x reference)
#include <cuda_runtime.h>

// Problem constants (match reference)
#define Hc 2048
#define Wc 2048
#define UH 2049   // u rows
#define UW 2048   // u cols
#define VH 2048   // v rows
#define VW 2049   // v cols
#define DT 0.01f
#define VISC 0.001f

// Device scratch (allocation-free rule: use __device__ globals)
__device__ float g_u  [UH * UW];
__device__ float g_v  [VH * VW];
__device__ float g_u2 [UH * UW];
__device__ float g_v2 [VH * VW];
__device__ float g_dens[Hc * Wc];
__device__ float g_div [Hc * Wc];
__device__ float g_p  [Hc * Wc];
__device__ float g_p2 [Hc * Wc];

__device__ __forceinline__ float bilerp(const float* __restrict__ f, int h, int w,
                                        float y, float x) {
    int x0 = (int)floorf(x);
    int x1 = x0 + 1;
    int y0 = (int)floorf(y);
    int y1 = y0 + 1;
    x0 = min(max(x0, 0), w - 1);
    x1 = min(max(x1, 0), w - 1);
    y0 = min(max(y0, 0), h - 1);
    y1 = min(max(y1, 0), h - 1);
    float x0f = (float)x0, x1f = (float)x1;
    float y0f = (float)y0, y1f = (float)y1;
    float wa = (x1f - x) * (y1f - y);
    float wb = (x - x0f) * (y1f - y);
    float wc = (x1f - x) * (y - y0f);
    float wd = (x - x0f) * (y - y0f);
    return wa * f[y0 * w + x0] + wb * f[y0 * w + x1]
         + wc * f[y1 * w + x0] + wd * f[y1 * w + x1];
}

// ---- diffuse (edge-padded 5-point) ----
__global__ void diffuse_kernel(const float* __restrict__ f, float* __restrict__ out,
                               int h, int w, float a) {
    int j = blockIdx.x * blockDim.x + threadIdx.x;
    int i = blockIdx.y * blockDim.y + threadIdx.y;
    if (i >= h || j >= w) return;
    float c  = f[i * w + j];
    float up = f[max(i - 1, 0) * w + j];
    float dn = f[min(i + 1, h - 1) * w + j];
    float lf = f[i * w + max(j - 1, 0)];
    float rt = f[i * w + min(j + 1, w - 1)];
    out[i * w + j] = c + a * (up + dn + lf + rt - 4.0f * c);
}

// ---- diffuse v with force v[:, :W] += DT*0.1*density applied on the fly ----
__device__ __forceinline__ float vforce(const float* __restrict__ v,
                                        const float* __restrict__ dens,
                                        int i, int j) {
    float val = v[i * VW + j];
    if (j < Wc) val += (DT * 0.1f) * dens[i * Wc + j];
    return val;
}

__global__ void diffuse_v_force_kernel(const float* __restrict__ v,
                                       const float* __restrict__ dens,
                                       float* __restrict__ out, float a) {
    int j = blockIdx.x * blockDim.x + threadIdx.x;
    int i = blockIdx.y * blockDim.y + threadIdx.y;
    if (i >= VH || j >= VW) return;
    float c  = vforce(v, dens, i, j);
    float up = vforce(v, dens, max(i - 1, 0), j);
    float dn = vforce(v, dens, min(i + 1, VH - 1), j);
    float lf = vforce(v, dens, i, max(j - 1, 0));
    float rt = vforce(v, dens, i, min(j + 1, VW - 1));
    out[i * VW + j] = c + a * (up + dn + lf + rt - 4.0f * c);
}

// ---- divergence ----
__global__ void div_kernel(const float* __restrict__ u, const float* __restrict__ v,
                           float* __restrict__ dv) {
    int j = blockIdx.x * blockDim.x + threadIdx.x;
    int i = blockIdx.y * blockDim.y + threadIdx.y;
    if (i >= Hc || j >= Wc) return;
    float d = (u[(i + 1) * UW + j] - u[i * UW + j]
             + v[i * VW + j + 1]  - v[i * VW + j]) / DT;
    dv[i * Wc + j] = d;
}

// ---- Jacobi: first iteration (p == 0) ----
__global__ void jacobi0_kernel(const float* __restrict__ dv, float* __restrict__ pout) {
    int j = blockIdx.x * blockDim.x + threadIdx.x;
    int i = blockIdx.y * blockDim.y + threadIdx.y;
    if (i >= Hc || j >= Wc) return;
    float r = 0.0f;
    if (i > 0 && j > 0 && i < Hc - 1 && j < Wc - 1)
        r = -0.25f * dv[i * Wc + j];
    pout[i * Wc + j] = r;
}

// ---- Jacobi iteration ----
__global__ void jacobi_kernel(const float* __restrict__ pin, const float* __restrict__ dv,
                              float* __restrict__ pout) {
    int j = blockIdx.x * blockDim.x + threadIdx.x;
    int i = blockIdx.y * blockDim.y + threadIdx.y;
    if (i >= Hc || j >= Wc) return;
    float r = 0.0f;
    if (i > 0 && j > 0 && i < Hc - 1 && j < Wc - 1) {
        r = 0.25f * (pin[(i - 1) * Wc + j] + pin[(i + 1) * Wc + j]
                   + pin[i * Wc + j - 1]   + pin[i * Wc + j + 1]
                   - dv[i * Wc + j]);
    }
    pout[i * Wc + j] = r;
}

// ---- subtract pressure gradient (in place) ----
__global__ void grad_u_kernel(float* __restrict__ u, const float* __restrict__ p) {
    int j = blockIdx.x * blockDim.x + threadIdx.x;
    int i = blockIdx.y * blockDim.y + threadIdx.y + 1;   // u rows 1..UH-2 (=2047)
    if (i > UH - 2 || j >= UW) return;
    u[i * UW + j] -= DT * (p[i * Wc + j] - p[(i - 1) * Wc + j]);
}

__global__ void grad_v_kernel(float* __restrict__ v, const float* __restrict__ p) {
    int j = blockIdx.x * blockDim.x + threadIdx.x + 1;   // v cols 1..VW-2 (=2047)
    int i = blockIdx.y * blockDim.y + threadIdx.y;
    if (i >= VH || j > VW - 2) return;
    v[i * VW + j] -= DT * (p[i * Wc + j] - p[i * Wc + j - 1]);
}

// ---- advect u (field = u, velocities u_old, v_old) ----
__global__ void advect_u_kernel(const float* __restrict__ u, const float* __restrict__ v,
                                float* __restrict__ out) {
    int j = blockIdx.x * blockDim.x + threadIdx.x;
    int i = blockIdx.y * blockDim.y + threadIdx.y;
    if (i >= UH || j >= UW) return;
    float Y = (float)i, X = (float)j;
    float x_u = fminf(fmaxf(X + 0.5f, 0.0f), (float)(UW - 1));
    float u_i = bilerp(u, UH, UW, Y, x_u);
    float y_v = fminf(fmaxf(Y + 0.5f, 0.0f), (float)(VH - 1));
    float v_i = bilerp(v, VH, VW, y_v, X);
    float px = fminf(fmaxf(X - DT * u_i, 0.0f), (float)(UW - 1));
    float py = fminf(fmaxf(Y - DT * v_i, 0.0f), (float)(UH - 1));
    out[i * UW + j] = bilerp(u, UH, UW, py, px);
}

// ---- advect v (field = v_old, velocities u_NEW, v_old) ----
__global__ void advect_v_kernel(const float* __restrict__ vold, const float* __restrict__ unew,
                                float* __restrict__ out) {
    int j = blockIdx.x * blockDim.x + threadIdx.x;
    int i = blockIdx.y * blockDim.y + threadIdx.y;
    if (i >= VH || j >= VW) return;
    float Y = (float)i, X = (float)j;
    float x_u = fminf(fmaxf(X + 0.5f, 0.0f), (float)(UW - 1));
    float u_i = bilerp(unew, UH, UW, Y, x_u);
    float y_v = fminf(fmaxf(Y + 0.5f, 0.0f), (float)(VH - 1));
    float v_i = bilerp(vold, VH, VW, y_v, X);
    float px = fminf(fmaxf(X - DT * u_i, 0.0f), (float)(VW - 1));
    float py = fminf(fmaxf(Y - DT * v_i, 0.0f), (float)(VH - 1));
    out[i * VW + j] = bilerp(vold, VH, VW, py, px);
}

// ---- advect density (field = dens_diffused, velocities u_NEW, v_NEW) + 0.995 decay ----
__global__ void advect_dens_kernel(const float* __restrict__ dens,
                                   const float* __restrict__ unew,
                                   const float* __restrict__ vnew,
                                   float* __restrict__ out) {
    int j = blockIdx.x * blockDim.x + threadIdx.x;
    int i = blockIdx.y * blockDim.y + threadIdx.y;
    if (i >= Hc || j >= Wc) return;
    float Y = (float)i, X = (float)j;
    float x_u = fminf(fmaxf(X + 0.5f, 0.0f), (float)(UW - 1));
    float u_i = bilerp(unew, UH, UW, Y, x_u);
    float y_v = fminf(fmaxf(Y + 0.5f, 0.0f), (float)(VH - 1));
    float v_i = bilerp(vnew, VH, VW, y_v, X);
    float px = fminf(fmaxf(X - DT * u_i, 0.0f), (float)(Wc - 1));
    float py = fminf(fmaxf(Y - DT * v_i, 0.0f), (float)(Hc - 1));
    out[i * Wc + j] = 0.995f * bilerp(dens, Hc, Wc, py, px);
}

extern "C" void kernel_launch(void* const* d_in, const int* in_sizes, int n_in,
                              void* d_out, int out_size) {
    const float* u_in    = (const float*)d_in[0];   // (2049, 2048)
    const float* v_in    = (const float*)d_in[1];   // (2048, 2049)
    const float* dens_in = (const float*)d_in[2];   // (2048, 2048)
    // d_in[3] = p (zeros) — unused; we build p from scratch deterministically.
    float* out = (float*)d_out;

    float *du, *dv_, *du2, *dv2, *dd, *ddiv, *dp, *dp2;
    cudaGetSymbolAddress((void**)&du,   g_u);
    cudaGetSymbolAddress((void**)&dv_,  g_v);
    cudaGetSymbolAddress((void**)&du2,  g_u2);
    cudaGetSymbolAddress((void**)&dv2,  g_v2);
    cudaGetSymbolAddress((void**)&dd,   g_dens);
    cudaGetSymbolAddress((void**)&ddiv, g_div);
    cudaGetSymbolAddress((void**)&dp,   g_p);
    cudaGetSymbolAddress((void**)&dp2,  g_p2);

    dim3 blk(128, 2);
    dim3 grdU((UW + blk.x - 1) / blk.x, (UH + blk.y - 1) / blk.y);
    dim3 grdV((VW + blk.x - 1) / blk.x, (VH + blk.y - 1) / blk.y);
    dim3 grdS((Wc + blk.x - 1) / blk.x, (Hc + blk.y - 1) / blk.y);

    // 1. diffuse u / (force + diffuse) v / diffuse density
    diffuse_kernel<<<grdU, blk>>>(u_in, du, UH, UW, DT * VISC);
    diffuse_v_force_kernel<<<grdV, blk>>>(v_in, dens_in, dv_, DT * VISC);
    diffuse_kernel<<<grdS, blk>>>(dens_in, dd, Hc, Wc, DT * VISC * 0.1f);

    // 2. divergence
    div_kernel<<<grdS, blk>>>(du, dv_, ddiv);

    // 3. Jacobi 20 iterations (first one exploits p==0), ping-pong ends in dp
    jacobi0_kernel<<<grdS, blk>>>(ddiv, dp2);
    for (int it = 1; it < 20; it++) {
        if (it & 1) jacobi_kernel<<<grdS, blk>>>(dp2, ddiv, dp);
        else        jacobi_kernel<<<grdS, blk>>>(dp, ddiv, dp2);
    }
    // iters: 0 writes dp2; odd its write dp; even write dp2. it=19 (odd) -> dp. Final in dp.

    // 4. pressure projection (in place on du, dv_)
    {
        dim3 grdGU((UW + blk.x - 1) / blk.x, ((UH - 2) + blk.y - 1) / blk.y);
        grad_u_kernel<<<grdGU, blk>>>(du, dp);
        dim3 grdGV(((VW - 2) + blk.x - 1) / blk.x, (VH + blk.y - 1) / blk.y);
        grad_v_kernel<<<grdGV, blk>>>(dv_, dp);
    }

    // 5. advect: u first (old u,v), then v (new u, old v), then density (new u,v)
    advect_u_kernel<<<grdU, blk>>>(du, dv_, du2);
    advect_v_kernel<<<grdV, blk>>>(dv_, du2, dv2);
    advect_dens_kernel<<<grdS, blk>>>(dd, du2, dv2, out);
}

// round 2
// speedup vs baseline: 1.1619x; 1.1619x over previous
#include <cuda_runtime.h>

#define Hc 2048
#define Wc 2048
#define UH 2049
#define UW 2048
#define VH 2048
#define VW 2049
#define DT 0.01f
#define VISC 0.001f

// Device scratch
__device__ float g_u  [UH * UW];
__device__ float g_v  [VH * VW];
__device__ float g_u2 [UH * UW];
__device__ float g_v2 [VH * VW];
__device__ float g_dens[Hc * Wc];
__device__ float g_div [Hc * Wc];
__device__ float g_p  [Hc * Wc];
__device__ float g_p2 [Hc * Wc];

__device__ __forceinline__ float bilerp(const float* __restrict__ f, int h, int w,
                                        float y, float x) {
    int x0 = (int)floorf(x);
    int x1 = x0 + 1;
    int y0 = (int)floorf(y);
    int y1 = y0 + 1;
    x0 = min(max(x0, 0), w - 1);
    x1 = min(max(x1, 0), w - 1);
    y0 = min(max(y0, 0), h - 1);
    y1 = min(max(y1, 0), h - 1);
    float x0f = (float)x0, x1f = (float)x1;
    float y0f = (float)y0, y1f = (float)y1;
    float wa = (x1f - x) * (y1f - y);
    float wb = (x - x0f) * (y1f - y);
    float wc = (x1f - x) * (y - y0f);
    float wd = (x - x0f) * (y - y0f);
    return wa * f[y0 * w + x0] + wb * f[y0 * w + x1]
         + wc * f[y1 * w + x0] + wd * f[y1 * w + x1];
}

// ---- diffuse, float4 (w % 4 == 0) ----
__global__ void diffuse_f4_kernel(const float* __restrict__ f, float* __restrict__ out,
                                  int h, int w, float a) {
    int qx = blockIdx.x * blockDim.x + threadIdx.x;
    int i  = blockIdx.y * blockDim.y + threadIdx.y;
    int w4 = w >> 2;
    if (i >= h || qx >= w4) return;
    int j0 = qx * 4;
    const float4* f4 = (const float4*)f;
    float4 c  = f4[i * w4 + qx];
    int iu = max(i - 1, 0), id = min(i + 1, h - 1);
    float4 up = f4[iu * w4 + qx];
    float4 dn = f4[id * w4 + qx];
    float lf = (j0 > 0)       ? f[i * w + j0 - 1] : c.x;
    float rt = (j0 + 4 < w)   ? f[i * w + j0 + 4] : c.w;
    float4 r;
    r.x = c.x + a * (up.x + dn.x + lf  + c.y - 4.0f * c.x);
    r.y = c.y + a * (up.y + dn.y + c.x + c.z - 4.0f * c.y);
    r.z = c.z + a * (up.z + dn.z + c.y + c.w - 4.0f * c.z);
    r.w = c.w + a * (up.w + dn.w + c.z + rt  - 4.0f * c.w);
    ((float4*)out)[i * w4 + qx] = r;
}

// ---- diffuse v with force (scalar; VW=2049 unaligned) ----
__device__ __forceinline__ float vforce(const float* __restrict__ v,
                                        const float* __restrict__ dens,
                                        int i, int j) {
    float val = v[i * VW + j];
    if (j < Wc) val += (DT * 0.1f) * dens[i * Wc + j];
    return val;
}

__global__ void diffuse_v_force_kernel(const float* __restrict__ v,
                                       const float* __restrict__ dens,
                                       float* __restrict__ out, float a) {
    int j = blockIdx.x * blockDim.x + threadIdx.x;
    int i = blockIdx.y * blockDim.y + threadIdx.y;
    if (i >= VH || j >= VW) return;
    float c  = vforce(v, dens, i, j);
    float up = vforce(v, dens, max(i - 1, 0), j);
    float dn = vforce(v, dens, min(i + 1, VH - 1), j);
    float lf = vforce(v, dens, i, max(j - 1, 0));
    float rt = vforce(v, dens, i, min(j + 1, VW - 1));
    out[i * VW + j] = c + a * (up + dn + lf + rt - 4.0f * c);
}

// ---- divergence, float4 for u, scalar for v ----
__global__ void div_f4_kernel(const float* __restrict__ u, const float* __restrict__ v,
                              float* __restrict__ dv) {
    int qx = blockIdx.x * blockDim.x + threadIdx.x;
    int i  = blockIdx.y * blockDim.y + threadIdx.y;
    int w4 = Wc >> 2;
    if (i >= Hc || qx >= w4) return;
    int j0 = qx * 4;
    const float4* u4 = (const float4*)u;
    float4 u0 = u4[i * w4 + qx];
    float4 u1 = u4[(i + 1) * w4 + qx];
    const float* vr = v + i * VW + j0;
    float v0 = vr[0], v1 = vr[1], v2 = vr[2], v3 = vr[3], v4 = vr[4];
    float4 r;
    r.x = (u1.x - u0.x + v1 - v0) / DT;
    r.y = (u1.y - u0.y + v2 - v1) / DT;
    r.z = (u1.z - u0.z + v3 - v2) / DT;
    r.w = (u1.w - u0.w + v4 - v3) / DT;
    ((float4*)dv)[i * w4 + qx] = r;
}

// ---- fused 4x Jacobi with shared-memory tiling ----
#define JT 4
#define TBX 64
#define TBY 32
#define SW (TBX + 2 * JT)   // 72
#define SH (TBY + 2 * JT)   // 40

__global__ void __launch_bounds__(512)
jacobi4_kernel(const float* __restrict__ pin, const float* __restrict__ dv,
               float* __restrict__ pout, int p_zero) {
    __shared__ float sA[SH][SW + 1];
    __shared__ float sB[SH][SW + 1];
    __shared__ float sD[SH][SW + 1];
    int bx0 = blockIdx.x * TBX, by0 = blockIdx.y * TBY;
    int tid = threadIdx.y * 64 + threadIdx.x;

    for (int idx = tid; idx < SH * SW; idx += 512) {
        int y = idx / SW, x = idx - y * SW;
        int gy = by0 + y - JT, gx = bx0 + x - JT;
        bool in = (gy >= 0 && gy < Hc && gx >= 0 && gx < Wc);
        sD[y][x] = in ? dv[gy * Wc + gx] : 0.0f;
        sA[y][x] = (in && !p_zero) ? pin[gy * Wc + gx] : 0.0f;
    }
    __syncthreads();

    #pragma unroll
    for (int t = 1; t <= JT; t++) {
        float (*src)[SW + 1] = (t & 1) ? sA : sB;
        float (*dst)[SW + 1] = (t & 1) ? sB : sA;
        for (int y = t + threadIdx.y; y < SH - t; y += 8) {
            int gy = by0 + y - JT;
            bool rin = (gy >= 1 && gy <= Hc - 2);
            for (int x = t + threadIdx.x; x < SW - t; x += 64) {
                int gx = bx0 + x - JT;
                float r = 0.0f;
                if (rin && gx >= 1 && gx <= Wc - 2)
                    r = 0.25f * (src[y - 1][x] + src[y + 1][x]
                               + src[y][x - 1] + src[y][x + 1] - sD[y][x]);
                dst[y][x] = r;
            }
        }
        __syncthreads();
    }
    // after t=4 (even), result is in sA
    for (int y = JT + threadIdx.y; y < SH - JT; y += 8) {
        int gy = by0 + y - JT;
        for (int x = JT + threadIdx.x; x < SW - JT; x += 64) {
            int gx = bx0 + x - JT;
            pout[gy * Wc + gx] = sA[y][x];
        }
    }
}

// ---- pressure gradient, float4 for u ----
__global__ void grad_u_f4_kernel(float* __restrict__ u, const float* __restrict__ p) {
    int qx = blockIdx.x * blockDim.x + threadIdx.x;
    int i  = blockIdx.y * blockDim.y + threadIdx.y + 1;   // rows 1..2047
    int w4 = Wc >> 2;
    if (i > UH - 2 || qx >= w4) return;
    const float4* p4 = (const float4*)p;
    float4 pc = p4[i * w4 + qx];
    float4 pm = p4[(i - 1) * w4 + qx];
    float4* u4 = (float4*)u;
    float4 uu = u4[i * w4 + qx];
    uu.x -= DT * (pc.x - pm.x);
    uu.y -= DT * (pc.y - pm.y);
    uu.z -= DT * (pc.z - pm.z);
    uu.w -= DT * (pc.w - pm.w);
    u4[i * w4 + qx] = uu;
}

__global__ void grad_v_kernel(float* __restrict__ v, const float* __restrict__ p) {
    int j = blockIdx.x * blockDim.x + threadIdx.x + 1;   // cols 1..2047
    int i = blockIdx.y * blockDim.y + threadIdx.y;
    if (i >= VH || j > VW - 2) return;
    v[i * VW + j] -= DT * (p[i * Wc + j] - p[i * Wc + j - 1]);
}

// ---- advects (scalar, gather) ----
__global__ void advect_u_kernel(const float* __restrict__ u, const float* __restrict__ v,
                                float* __restrict__ out) {
    int j = blockIdx.x * blockDim.x + threadIdx.x;
    int i = blockIdx.y * blockDim.y + threadIdx.y;
    if (i >= UH || j >= UW) return;
    float Y = (float)i, X = (float)j;
    float x_u = fminf(fmaxf(X + 0.5f, 0.0f), (float)(UW - 1));
    float u_i = bilerp(u, UH, UW, Y, x_u);
    float y_v = fminf(fmaxf(Y + 0.5f, 0.0f), (float)(VH - 1));
    float v_i = bilerp(v, VH, VW, y_v, X);
    float px = fminf(fmaxf(X - DT * u_i, 0.0f), (float)(UW - 1));
    float py = fminf(fmaxf(Y - DT * v_i, 0.0f), (float)(UH - 1));
    out[i * UW + j] = bilerp(u, UH, UW, py, px);
}

__global__ void advect_v_kernel(const float* __restrict__ vold, const float* __restrict__ unew,
                                float* __restrict__ out) {
    int j = blockIdx.x * blockDim.x + threadIdx.x;
    int i = blockIdx.y * blockDim.y + threadIdx.y;
    if (i >= VH || j >= VW) return;
    float Y = (float)i, X = (float)j;
    float x_u = fminf(fmaxf(X + 0.5f, 0.0f), (float)(UW - 1));
    float u_i = bilerp(unew, UH, UW, Y, x_u);
    float y_v = fminf(fmaxf(Y + 0.5f, 0.0f), (float)(VH - 1));
    float v_i = bilerp(vold, VH, VW, y_v, X);
    float px = fminf(fmaxf(X - DT * u_i, 0.0f), (float)(VW - 1));
    float py = fminf(fmaxf(Y - DT * v_i, 0.0f), (float)(VH - 1));
    out[i * VW + j] = bilerp(vold, VH, VW, py, px);
}

__global__ void advect_dens_kernel(const float* __restrict__ dens,
                                   const float* __restrict__ unew,
                                   const float* __restrict__ vnew,
                                   float* __restrict__ out) {
    int j = blockIdx.x * blockDim.x + threadIdx.x;
    int i = blockIdx.y * blockDim.y + threadIdx.y;
    if (i >= Hc || j >= Wc) return;
    float Y = (float)i, X = (float)j;
    float x_u = fminf(fmaxf(X + 0.5f, 0.0f), (float)(UW - 1));
    float u_i = bilerp(unew, UH, UW, Y, x_u);
    float y_v = fminf(fmaxf(Y + 0.5f, 0.0f), (float)(VH - 1));
    float v_i = bilerp(vnew, VH, VW, y_v, X);
    float px = fminf(fmaxf(X - DT * u_i, 0.0f), (float)(Wc - 1));
    float py = fminf(fmaxf(Y - DT * v_i, 0.0f), (float)(Hc - 1));
    out[i * Wc + j] = 0.995f * bilerp(dens, Hc, Wc, py, px);
}

extern "C" void kernel_launch(void* const* d_in, const int* in_sizes, int n_in,
                              void* d_out, int out_size) {
    const float* u_in    = (const float*)d_in[0];
    const float* v_in    = (const float*)d_in[1];
    const float* dens_in = (const float*)d_in[2];
    float* out = (float*)d_out;

    float *du, *dv_, *du2, *dv2, *dd, *ddiv, *dp, *dp2;
    cudaGetSymbolAddress((void**)&du,   g_u);
    cudaGetSymbolAddress((void**)&dv_,  g_v);
    cudaGetSymbolAddress((void**)&du2,  g_u2);
    cudaGetSymbolAddress((void**)&dv2,  g_v2);
    cudaGetSymbolAddress((void**)&dd,   g_dens);
    cudaGetSymbolAddress((void**)&ddiv, g_div);
    cudaGetSymbolAddress((void**)&dp,   g_p);
    cudaGetSymbolAddress((void**)&dp2,  g_p2);

    // float4 kernels: blockDim (64,4) -> tile 256x4
    dim3 blkQ(64, 4);
    int w4 = Wc >> 2;
    dim3 grdQ_U((w4 + 63) / 64, (UH + 3) / 4);
    dim3 grdQ_S((w4 + 63) / 64, (Hc + 3) / 4);

    // scalar kernels
    dim3 blkS(128, 2);
    dim3 grdV((VW + 127) / 128, (VH + 1) / 2);
    dim3 grdU((UW + 127) / 128, (UH + 1) / 2);
    dim3 grdS((Wc + 127) / 128, (Hc + 1) / 2);

    // 1. diffuse
    diffuse_f4_kernel<<<grdQ_U, blkQ>>>(u_in, du, UH, UW, DT * VISC);
    diffuse_v_force_kernel<<<grdV, blkS>>>(v_in, dens_in, dv_, DT * VISC);
    diffuse_f4_kernel<<<grdQ_S, blkQ>>>(dens_in, dd, Hc, Wc, DT * VISC * 0.1f);

    // 2. divergence
    div_f4_kernel<<<grdQ_S, blkQ>>>(du, dv_, ddiv);

    // 3. 20 Jacobi iterations = 5 fused x4 launches
    {
        dim3 blkJ(64, 8);
        dim3 grdJ(Wc / TBX, Hc / TBY);   // 32 x 64
        jacobi4_kernel<<<grdJ, blkJ>>>(dp2, ddiv, dp, 1);   // iters 1-4 (p0 = 0)
        jacobi4_kernel<<<grdJ, blkJ>>>(dp, ddiv, dp2, 0);   // 5-8
        jacobi4_kernel<<<grdJ, blkJ>>>(dp2, ddiv, dp, 0);   // 9-12
        jacobi4_kernel<<<grdJ, blkJ>>>(dp, ddiv, dp2, 0);   // 13-16
        jacobi4_kernel<<<grdJ, blkJ>>>(dp2, ddiv, dp, 0);   // 17-20 -> dp
    }

    // 4. projection
    {
        dim3 grdGU((w4 + 63) / 64, ((UH - 2) + 3) / 4);
        grad_u_f4_kernel<<<grdGU, blkQ>>>(du, dp);
        dim3 grdGV(((VW - 2) + 127) / 128, (VH + 1) / 2);
        grad_v_kernel<<<grdGV, blkS>>>(dv_, dp);
    }

    // 5. advect
    advect_u_kernel<<<grdU, blkS>>>(du, dv_, du2);
    advect_v_kernel<<<grdV, blkS>>>(dv_, du2, dv2);
    advect_dens_kernel<<<grdS, blkS>>>(dd, du2, dv2, out);
}

// round 3
// speedup vs baseline: 1.2759x; 1.0982x over previous
#include <cuda_runtime.h>

#define Hc 2048
#define Wc 2048
#define UH 2049
#define UW 2048
#define VH 2048
#define VW 2049
#define DT 0.01f
#define VISC 0.001f

// Device scratch
__device__ float g_u  [UH * UW];
__device__ float g_v  [VH * VW];
__device__ float g_u2 [UH * UW];
__device__ float g_v2 [VH * VW];
__device__ float g_dens[Hc * Wc];
__device__ float g_div [Hc * Wc];
__device__ float g_p  [Hc * Wc];
__device__ float g_p2 [Hc * Wc];

__device__ __forceinline__ float bilerp(const float* __restrict__ f, int h, int w,
                                        float y, float x) {
    int x0 = (int)floorf(x);
    int x1 = x0 + 1;
    int y0 = (int)floorf(y);
    int y1 = y0 + 1;
    x0 = min(max(x0, 0), w - 1);
    x1 = min(max(x1, 0), w - 1);
    y0 = min(max(y0, 0), h - 1);
    y1 = min(max(y1, 0), h - 1);
    float x0f = (float)x0, x1f = (float)x1;
    float y0f = (float)y0, y1f = (float)y1;
    float wa = (x1f - x) * (y1f - y);
    float wb = (x - x0f) * (y1f - y);
    float wc = (x1f - x) * (y - y0f);
    float wd = (x - x0f) * (y - y0f);
    return wa * f[y0 * w + x0] + wb * f[y0 * w + x1]
         + wc * f[y1 * w + x0] + wd * f[y1 * w + x1];
}

// ---- diffuse, float4 ----
__global__ void diffuse_f4_kernel(const float* __restrict__ f, float* __restrict__ out,
                                  int h, int w, float a) {
    int qx = blockIdx.x * blockDim.x + threadIdx.x;
    int i  = blockIdx.y * blockDim.y + threadIdx.y;
    int w4 = w >> 2;
    if (i >= h || qx >= w4) return;
    int j0 = qx * 4;
    const float4* f4 = (const float4*)f;
    float4 c  = f4[i * w4 + qx];
    int iu = max(i - 1, 0), id = min(i + 1, h - 1);
    float4 up = f4[iu * w4 + qx];
    float4 dn = f4[id * w4 + qx];
    float lf = (j0 > 0)       ? f[i * w + j0 - 1] : c.x;
    float rt = (j0 + 4 < w)   ? f[i * w + j0 + 4] : c.w;
    float4 r;
    r.x = c.x + a * (up.x + dn.x + lf  + c.y - 4.0f * c.x);
    r.y = c.y + a * (up.y + dn.y + c.x + c.z - 4.0f * c.y);
    r.z = c.z + a * (up.z + dn.z + c.y + c.w - 4.0f * c.z);
    r.w = c.w + a * (up.w + dn.w + c.z + rt  - 4.0f * c.w);
    ((float4*)out)[i * w4 + qx] = r;
}

// ---- diffuse v with force (scalar; VW=2049 unaligned) ----
__device__ __forceinline__ float vforce(const float* __restrict__ v,
                                        const float* __restrict__ dens,
                                        int i, int j) {
    float val = v[i * VW + j];
    if (j < Wc) val += (DT * 0.1f) * dens[i * Wc + j];
    return val;
}

__global__ void diffuse_v_force_kernel(const float* __restrict__ v,
                                       const float* __restrict__ dens,
                                       float* __restrict__ out, float a) {
    int j = blockIdx.x * blockDim.x + threadIdx.x;
    int i = blockIdx.y * blockDim.y + threadIdx.y;
    if (i >= VH || j >= VW) return;
    float c  = vforce(v, dens, i, j);
    float up = vforce(v, dens, max(i - 1, 0), j);
    float dn = vforce(v, dens, min(i + 1, VH - 1), j);
    float lf = vforce(v, dens, i, max(j - 1, 0));
    float rt = vforce(v, dens, i, min(j + 1, VW - 1));
    out[i * VW + j] = c + a * (up + dn + lf + rt - 4.0f * c);
}

// ---- divergence, float4 for u, scalar for v ----
__global__ void div_f4_kernel(const float* __restrict__ u, const float* __restrict__ v,
                              float* __restrict__ dv) {
    int qx = blockIdx.x * blockDim.x + threadIdx.x;
    int i  = blockIdx.y * blockDim.y + threadIdx.y;
    int w4 = Wc >> 2;
    if (i >= Hc || qx >= w4) return;
    int j0 = qx * 4;
    const float4* u4 = (const float4*)u;
    float4 u0 = u4[i * w4 + qx];
    float4 u1 = u4[(i + 1) * w4 + qx];
    const float* vr = v + i * VW + j0;
    float v0 = vr[0], v1 = vr[1], v2 = vr[2], v3 = vr[3], v4 = vr[4];
    float4 r;
    r.x = (u1.x - u0.x + v1 - v0) / DT;
    r.y = (u1.y - u0.y + v2 - v1) / DT;
    r.z = (u1.z - u0.z + v3 - v2) / DT;
    r.w = (u1.w - u0.w + v4 - v3) / DT;
    ((float4*)dv)[i * w4 + qx] = r;
}

// ---- fused 4x Jacobi, trapezoid tiling, 64x64 output tile ----
#define JT 4
#define TBX 64
#define TBY 64
#define SW (TBX + 2 * JT)   // 72
#define SH (TBY + 2 * JT)   // 72
#define SWP (SW + 1)        // 73 (pad)

__global__ void __launch_bounds__(512, 3)
jacobi4_kernel(const float* __restrict__ pin, const float* __restrict__ dv,
               float* __restrict__ pout, int p_zero) {
    extern __shared__ float smem[];
    float* sA = smem;                 // SH*SWP
    float* sB = smem + SH * SWP;
    float* sD = smem + 2 * SH * SWP;

    int bx0 = blockIdx.x * TBX - JT;   // gx = bx0 + x
    int by0 = blockIdx.y * TBY - JT;
    int tx = threadIdx.x, ty = threadIdx.y;
    int tid = ty * 64 + tx;
    bool border = (blockIdx.x == 0 || blockIdx.y == 0 ||
                   blockIdx.x == gridDim.x - 1 || blockIdx.y == gridDim.y - 1);

    // Load tile + halo
    if (!border) {
        if (p_zero) {
            for (int idx = tid; idx < SH * SW; idx += 512) {
                int y = idx / SW, x = idx - y * SW;
                sD[y * SWP + x] = dv[(by0 + y) * Wc + bx0 + x];
                sA[y * SWP + x] = 0.0f;
            }
        } else {
            for (int idx = tid; idx < SH * SW; idx += 512) {
                int y = idx / SW, x = idx - y * SW;
                int g = (by0 + y) * Wc + bx0 + x;
                sD[y * SWP + x] = dv[g];
                sA[y * SWP + x] = pin[g];
            }
        }
    } else {
        for (int idx = tid; idx < SH * SW; idx += 512) {
            int y = idx / SW, x = idx - y * SW;
            int gy = by0 + y, gx = bx0 + x;
            bool in = (gy >= 0 && gy < Hc && gx >= 0 && gx < Wc);
            sD[y * SWP + x] = in ? dv[gy * Wc + gx] : 0.0f;
            sA[y * SWP + x] = (in && !p_zero) ? pin[gy * Wc + gx] : 0.0f;
        }
    }
    __syncthreads();

    // 4 Jacobi iterations over the full smem interior (trapezoid validity:
    // edge-adjacent garbage never reaches the central 64x64 output).
    float* src = sA;
    float* dst = sB;
    #pragma unroll
    for (int t = 0; t < JT; t++) {
        if (!border) {
            #pragma unroll
            for (int yy = 1 + ty; yy <= SH - 2; yy += 8) {
                int row = yy * SWP;
                #pragma unroll
                for (int xx = 1 + tx; xx <= SW - 2; xx += 64) {
                    dst[row + xx] = 0.25f * (src[row - SWP + xx] + src[row + SWP + xx]
                                           + src[row + xx - 1]   + src[row + xx + 1]
                                           - sD[row + xx]);
                }
            }
        } else {
            #pragma unroll
            for (int yy = 1 + ty; yy <= SH - 2; yy += 8) {
                int row = yy * SWP;
                int gy = by0 + yy;
                bool rowin = (gy >= 1 && gy <= Hc - 2);
                #pragma unroll
                for (int xx = 1 + tx; xx <= SW - 2; xx += 64) {
                    int gx = bx0 + xx;
                    float r = 0.0f;
                    if (rowin && gx >= 1 && gx <= Wc - 2)
                        r = 0.25f * (src[row - SWP + xx] + src[row + SWP + xx]
                                   + src[row + xx - 1]   + src[row + xx + 1]
                                   - sD[row + xx]);
                    dst[row + xx] = r;
                }
            }
        }
        __syncthreads();
        float* tmp = src; src = dst; dst = tmp;
    }
    // after 4 iters result is in src

    // Store central 64x64
    for (int idx = tid; idx < TBX * TBY; idx += 512) {
        int y = idx / TBX, x = idx - y * TBX;
        pout[(blockIdx.y * TBY + y) * Wc + blockIdx.x * TBX + x]
            = src[(y + JT) * SWP + x + JT];
    }
}

// ---- pressure gradient, float4 for u ----
__global__ void grad_u_f4_kernel(float* __restrict__ u, const float* __restrict__ p) {
    int qx = blockIdx.x * blockDim.x + threadIdx.x;
    int i  = blockIdx.y * blockDim.y + threadIdx.y + 1;   // rows 1..2047
    int w4 = Wc >> 2;
    if (i > UH - 2 || qx >= w4) return;
    const float4* p4 = (const float4*)p;
    float4 pc = p4[i * w4 + qx];
    float4 pm = p4[(i - 1) * w4 + qx];
    float4* u4 = (float4*)u;
    float4 uu = u4[i * w4 + qx];
    uu.x -= DT * (pc.x - pm.x);
    uu.y -= DT * (pc.y - pm.y);
    uu.z -= DT * (pc.z - pm.z);
    uu.w -= DT * (pc.w - pm.w);
    u4[i * w4 + qx] = uu;
}

__global__ void grad_v_kernel(float* __restrict__ v, const float* __restrict__ p) {
    int j = blockIdx.x * blockDim.x + threadIdx.x + 1;   // cols 1..2047
    int i = blockIdx.y * blockDim.y + threadIdx.y;
    if (i >= VH || j > VW - 2) return;
    v[i * VW + j] -= DT * (p[i * Wc + j] - p[i * Wc + j - 1]);
}

// ---- advects (scalar, gather) ----
__global__ void advect_u_kernel(const float* __restrict__ u, const float* __restrict__ v,
                                float* __restrict__ out) {
    int j = blockIdx.x * blockDim.x + threadIdx.x;
    int i = blockIdx.y * blockDim.y + threadIdx.y;
    if (i >= UH || j >= UW) return;
    float Y = (float)i, X = (float)j;
    float x_u = fminf(fmaxf(X + 0.5f, 0.0f), (float)(UW - 1));
    float u_i = bilerp(u, UH, UW, Y, x_u);
    float y_v = fminf(fmaxf(Y + 0.5f, 0.0f), (float)(VH - 1));
    float v_i = bilerp(v, VH, VW, y_v, X);
    float px = fminf(fmaxf(X - DT * u_i, 0.0f), (float)(UW - 1));
    float py = fminf(fmaxf(Y - DT * v_i, 0.0f), (float)(UH - 1));
    out[i * UW + j] = bilerp(u, UH, UW, py, px);
}

__global__ void advect_v_kernel(const float* __restrict__ vold, const float* __restrict__ unew,
                                float* __restrict__ out) {
    int j = blockIdx.x * blockDim.x + threadIdx.x;
    int i = blockIdx.y * blockDim.y + threadIdx.y;
    if (i >= VH || j >= VW) return;
    float Y = (float)i, X = (float)j;
    float x_u = fminf(fmaxf(X + 0.5f, 0.0f), (float)(UW - 1));
    float u_i = bilerp(unew, UH, UW, Y, x_u);
    float y_v = fminf(fmaxf(Y + 0.5f, 0.0f), (float)(VH - 1));
    float v_i = bilerp(vold, VH, VW, y_v, X);
    float px = fminf(fmaxf(X - DT * u_i, 0.0f), (float)(VW - 1));
    float py = fminf(fmaxf(Y - DT * v_i, 0.0f), (float)(VH - 1));
    out[i * VW + j] = bilerp(vold, VH, VW, py, px);
}

__global__ void advect_dens_kernel(const float* __restrict__ dens,
                                   const float* __restrict__ unew,
                                   const float* __restrict__ vnew,
                                   float* __restrict__ out) {
    int j = blockIdx.x * blockDim.x + threadIdx.x;
    int i = blockIdx.y * blockDim.y + threadIdx.y;
    if (i >= Hc || j >= Wc) return;
    float Y = (float)i, X = (float)j;
    float x_u = fminf(fmaxf(X + 0.5f, 0.0f), (float)(UW - 1));
    float u_i = bilerp(unew, UH, UW, Y, x_u);
    float y_v = fminf(fmaxf(Y + 0.5f, 0.0f), (float)(VH - 1));
    float v_i = bilerp(vnew, VH, VW, y_v, X);
    float px = fminf(fmaxf(X - DT * u_i, 0.0f), (float)(Wc - 1));
    float py = fminf(fmaxf(Y - DT * v_i, 0.0f), (float)(Hc - 1));
    out[i * Wc + j] = 0.995f * bilerp(dens, Hc, Wc, py, px);
}

extern "C" void kernel_launch(void* const* d_in, const int* in_sizes, int n_in,
                              void* d_out, int out_size) {
    const float* u_in    = (const float*)d_in[0];
    const float* v_in    = (const float*)d_in[1];
    const float* dens_in = (const float*)d_in[2];
    float* out = (float*)d_out;

    float *du, *dv_, *du2, *dv2, *dd, *ddiv, *dp, *dp2;
    cudaGetSymbolAddress((void**)&du,   g_u);
    cudaGetSymbolAddress((void**)&dv_,  g_v);
    cudaGetSymbolAddress((void**)&du2,  g_u2);
    cudaGetSymbolAddress((void**)&dv2,  g_v2);
    cudaGetSymbolAddress((void**)&dd,   g_dens);
    cudaGetSymbolAddress((void**)&ddiv, g_div);
    cudaGetSymbolAddress((void**)&dp,   g_p);
    cudaGetSymbolAddress((void**)&dp2,  g_p2);

    // float4 kernels: blockDim (64,4)
    dim3 blkQ(64, 4);
    int w4 = Wc >> 2;
    dim3 grdQ_U((w4 + 63) / 64, (UH + 3) / 4);
    dim3 grdQ_S((w4 + 63) / 64, (Hc + 3) / 4);

    // scalar kernels
    dim3 blkS(128, 2);
    dim3 grdV((VW + 127) / 128, (VH + 1) / 2);
    dim3 grdU((UW + 127) / 128, (UH + 1) / 2);
    dim3 grdS((Wc + 127) / 128, (Hc + 1) / 2);

    // 1. diffuse
    diffuse_f4_kernel<<<grdQ_U, blkQ>>>(u_in, du, UH, UW, DT * VISC);
    diffuse_v_force_kernel<<<grdV, blkS>>>(v_in, dens_in, dv_, DT * VISC);
    diffuse_f4_kernel<<<grdQ_S, blkQ>>>(dens_in, dd, Hc, Wc, DT * VISC * 0.1f);

    // 2. divergence
    div_f4_kernel<<<grdQ_S, blkQ>>>(du, dv_, ddiv);

    // 3. 20 Jacobi iterations = 5 fused x4 launches
    {
        int jsmem = 3 * SH * SWP * (int)sizeof(float);   // ~63 KB
        static int attr_set = 0;
        if (!attr_set) {
            cudaFuncSetAttribute(jacobi4_kernel,
                                 cudaFuncAttributeMaxDynamicSharedMemorySize, jsmem);
            attr_set = 1;
        }
        dim3 blkJ(64, 8);
        dim3 grdJ(Wc / TBX, Hc / TBY);   // 32 x 32
        jacobi4_kernel<<<grdJ, blkJ, jsmem>>>(dp2, ddiv, dp, 1);   // iters 1-4 (p0=0)
        jacobi4_kernel<<<grdJ, blkJ, jsmem>>>(dp, ddiv, dp2, 0);   // 5-8
        jacobi4_kernel<<<grdJ, blkJ, jsmem>>>(dp2, ddiv, dp, 0);   // 9-12
        jacobi4_kernel<<<grdJ, blkJ, jsmem>>>(dp, ddiv, dp2, 0);   // 13-16
        jacobi4_kernel<<<grdJ, blkJ, jsmem>>>(dp2, ddiv, dp, 0);   // 17-20 -> dp
    }

    // 4. projection
    {
        dim3 grdGU((w4 + 63) / 64, ((UH - 2) + 3) / 4);
        grad_u_f4_kernel<<<grdGU, blkQ>>>(du, dp);
        dim3 grdGV(((VW - 2) + 127) / 128, (VH + 1) / 2);
        grad_v_kernel<<<grdGV, blkS>>>(dv_, dp);
    }

    // 5. advect
    advect_u_kernel<<<grdU, blkS>>>(du, dv_, du2);
    advect_v_kernel<<<grdV, blkS>>>(dv_, du2, dv2);
    advect_dens_kernel<<<grdS, blkS>>>(dd, du2, dv2, out);
}

// round 4
// speedup vs baseline: 1.6511x; 1.2941x over previous
#include <cuda_runtime.h>

#define Hc 2048
#define Wc 2048
#define UH 2049
#define UW 2048
#define VH 2048
#define VW 2049
#define DT 0.01f
#define VISC 0.001f

// Device scratch
__device__ float g_u  [UH * UW];
__device__ float g_v  [VH * VW];
__device__ float g_u2 [UH * UW];
__device__ float g_v2 [VH * VW];
__device__ float g_dens[Hc * Wc];
__device__ float g_div [Hc * Wc];
__device__ float g_p  [Hc * Wc];
__device__ float g_p2 [Hc * Wc];

__device__ __forceinline__ float bilerp(const float* __restrict__ f, int h, int w,
                                        float y, float x) {
    int x0 = (int)floorf(x);
    int x1 = x0 + 1;
    int y0 = (int)floorf(y);
    int y1 = y0 + 1;
    x0 = min(max(x0, 0), w - 1);
    x1 = min(max(x1, 0), w - 1);
    y0 = min(max(y0, 0), h - 1);
    y1 = min(max(y1, 0), h - 1);
    float x0f = (float)x0, x1f = (float)x1;
    float y0f = (float)y0, y1f = (float)y1;
    float wa = (x1f - x) * (y1f - y);
    float wb = (x - x0f) * (y1f - y);
    float wc = (x1f - x) * (y - y0f);
    float wd = (x - x0f) * (y - y0f);
    return wa * f[y0 * w + x0] + wb * f[y0 * w + x1]
         + wc * f[y1 * w + x0] + wd * f[y1 * w + x1];
}

// ---- diffuse, float4 ----
__global__ void diffuse_f4_kernel(const float* __restrict__ f, float* __restrict__ out,
                                  int h, int w, float a) {
    int qx = blockIdx.x * blockDim.x + threadIdx.x;
    int i  = blockIdx.y * blockDim.y + threadIdx.y;
    int w4 = w >> 2;
    if (i >= h || qx >= w4) return;
    int j0 = qx * 4;
    const float4* f4 = (const float4*)f;
    float4 c  = f4[i * w4 + qx];
    int iu = max(i - 1, 0), id = min(i + 1, h - 1);
    float4 up = f4[iu * w4 + qx];
    float4 dn = f4[id * w4 + qx];
    float lf = (j0 > 0)       ? f[i * w + j0 - 1] : c.x;
    float rt = (j0 + 4 < w)   ? f[i * w + j0 + 4] : c.w;
    float4 r;
    r.x = c.x + a * (up.x + dn.x + lf  + c.y - 4.0f * c.x);
    r.y = c.y + a * (up.y + dn.y + c.x + c.z - 4.0f * c.y);
    r.z = c.z + a * (up.z + dn.z + c.y + c.w - 4.0f * c.z);
    r.w = c.w + a * (up.w + dn.w + c.z + rt  - 4.0f * c.w);
    ((float4*)out)[i * w4 + qx] = r;
}

// ---- diffuse v with force ----
__device__ __forceinline__ float vforce(const float* __restrict__ v,
                                        const float* __restrict__ dens,
                                        int i, int j) {
    float val = v[i * VW + j];
    if (j < Wc) val += (DT * 0.1f) * dens[i * Wc + j];
    return val;
}

__global__ void diffuse_v_force_kernel(const float* __restrict__ v,
                                       const float* __restrict__ dens,
                                       float* __restrict__ out, float a) {
    int j = blockIdx.x * blockDim.x + threadIdx.x;
    int i = blockIdx.y * blockDim.y + threadIdx.y;
    if (i >= VH || j >= VW) return;
    float c  = vforce(v, dens, i, j);
    float up = vforce(v, dens, max(i - 1, 0), j);
    float dn = vforce(v, dens, min(i + 1, VH - 1), j);
    float lf = vforce(v, dens, i, max(j - 1, 0));
    float rt = vforce(v, dens, i, min(j + 1, VW - 1));
    out[i * VW + j] = c + a * (up + dn + lf + rt - 4.0f * c);
}

// ---- divergence ----
__global__ void div_f4_kernel(const float* __restrict__ u, const float* __restrict__ v,
                              float* __restrict__ dv) {
    int qx = blockIdx.x * blockDim.x + threadIdx.x;
    int i  = blockIdx.y * blockDim.y + threadIdx.y;
    int w4 = Wc >> 2;
    if (i >= Hc || qx >= w4) return;
    int j0 = qx * 4;
    const float4* u4 = (const float4*)u;
    float4 u0 = u4[i * w4 + qx];
    float4 u1 = u4[(i + 1) * w4 + qx];
    const float* vr = v + i * VW + j0;
    float v0 = vr[0], v1 = vr[1], v2 = vr[2], v3 = vr[3], v4 = vr[4];
    float4 r;
    r.x = (u1.x - u0.x + v1 - v0) / DT;
    r.y = (u1.y - u0.y + v2 - v1) / DT;
    r.z = (u1.z - u0.z + v3 - v2) / DT;
    r.w = (u1.w - u0.w + v4 - v3) / DT;
    ((float4*)dv)[i * w4 + qx] = r;
}

// ============ fused 4x Jacobi: 56x56 output tile, float4 + shfl ============
// smem tile: data rows 1..64 (66 rows alloc), row stride 68 floats.
#define OT 56
#define SSTRIDE 68
#define SROWS 66

__device__ __forceinline__ float4 jstep(const float* __restrict__ src, int r, int c,
                                        float4 dvv) {
    float4 up = *(const float4*)&src[(r - 1) * SSTRIDE + c];
    float4 dn = *(const float4*)&src[(r + 1) * SSTRIDE + c];
    float4 ce = *(const float4*)&src[r * SSTRIDE + c];
    float lf = __shfl_up_sync(0xffffffffu, ce.w, 1, 16);
    float rt = __shfl_down_sync(0xffffffffu, ce.x, 1, 16);
    float4 o;
    o.x = 0.25f * (up.x + dn.x + lf   + ce.y - dvv.x);
    o.y = 0.25f * (up.y + dn.y + ce.x + ce.z - dvv.y);
    o.z = 0.25f * (up.z + dn.z + ce.y + ce.w - dvv.z);
    o.w = 0.25f * (up.w + dn.w + ce.z + rt   - dvv.w);
    return o;
}

__device__ __forceinline__ float gload(const float* __restrict__ p, int gy, int gx) {
    return (gy >= 0 && gy < Hc && gx >= 0 && gx < Wc) ? p[gy * Wc + gx] : 0.0f;
}

__global__ void __launch_bounds__(512)
jacobi4_kernel(const float* __restrict__ pin, const float* __restrict__ dv,
               float* __restrict__ pout, int p_zero) {
    __shared__ float sA[SROWS * SSTRIDE];
    __shared__ float sB[SROWS * SSTRIDE];

    const int tx = threadIdx.x;           // 0..15
    const int ty = threadIdx.y;           // 0..31
    const int c  = tx * 4;
    const int bx0 = blockIdx.x * OT - 4;
    const int by0 = blockIdx.y * OT - 4;
    const bool border = (blockIdx.x == 0 || blockIdx.y == 0 ||
                         blockIdx.x == gridDim.x - 1 || blockIdx.y == gridDim.y - 1);

    const int gyA = by0 + ty;        // tile row ty
    const int gyB = by0 + ty + 32;   // tile row ty+32
    const int gx0 = bx0 + c;

    float4 dva, dvb;

    // ---- load p (or zeros) and div ----
    if (!border) {
        const float4* dv4 = (const float4*)dv;
        int gA = (gyA * Wc + gx0) >> 2;
        int gB = (gyB * Wc + gx0) >> 2;
        dva = dv4[gA];
        dvb = dv4[gB];
        if (p_zero) {
            float4 z = make_float4(0.f, 0.f, 0.f, 0.f);
            *(float4*)&sA[(ty + 1) * SSTRIDE + c]  = z;
            *(float4*)&sA[(ty + 33) * SSTRIDE + c] = z;
        } else {
            const float4* p4 = (const float4*)pin;
            *(float4*)&sA[(ty + 1) * SSTRIDE + c]  = p4[gA];
            *(float4*)&sA[(ty + 33) * SSTRIDE + c] = p4[gB];
        }
    } else {
        dva = make_float4(gload(dv, gyA, gx0),     gload(dv, gyA, gx0 + 1),
                          gload(dv, gyA, gx0 + 2), gload(dv, gyA, gx0 + 3));
        dvb = make_float4(gload(dv, gyB, gx0),     gload(dv, gyB, gx0 + 1),
                          gload(dv, gyB, gx0 + 2), gload(dv, gyB, gx0 + 3));
        float4 pa, pb;
        if (p_zero) {
            pa = make_float4(0.f, 0.f, 0.f, 0.f);
            pb = pa;
        } else {
            pa = make_float4(gload(pin, gyA, gx0),     gload(pin, gyA, gx0 + 1),
                             gload(pin, gyA, gx0 + 2), gload(pin, gyA, gx0 + 3));
            pb = make_float4(gload(pin, gyB, gx0),     gload(pin, gyB, gx0 + 1),
                             gload(pin, gyB, gx0 + 2), gload(pin, gyB, gx0 + 3));
        }
        *(float4*)&sA[(ty + 1) * SSTRIDE + c]  = pa;
        *(float4*)&sA[(ty + 33) * SSTRIDE + c] = pb;
    }
    __syncthreads();

    if (!border) {
        #pragma unroll
        for (int t = 0; t < 4; t++) {
            const float* src = (t & 1) ? sB : sA;
            float* dst       = (t & 1) ? sA : sB;
            float4 oa = jstep(src, ty + 1, c, dva);
            float4 ob = jstep(src, ty + 33, c, dvb);
            *(float4*)&dst[(ty + 1) * SSTRIDE + c]  = oa;
            *(float4*)&dst[(ty + 33) * SSTRIDE + c] = ob;
            __syncthreads();
        }
    } else {
        // per-component domain-interior masks (loop-invariant)
        bool rokA = (gyA >= 1 && gyA <= Hc - 2);
        bool rokB = (gyB >= 1 && gyB <= Hc - 2);
        bool ok0 = (gx0     >= 1 && gx0     <= Wc - 2);
        bool ok1 = (gx0 + 1 >= 1 && gx0 + 1 <= Wc - 2);
        bool ok2 = (gx0 + 2 >= 1 && gx0 + 2 <= Wc - 2);
        bool ok3 = (gx0 + 3 >= 1 && gx0 + 3 <= Wc - 2);
        #pragma unroll
        for (int t = 0; t < 4; t++) {
            const float* src = (t & 1) ? sB : sA;
            float* dst       = (t & 1) ? sA : sB;
            float4 oa = jstep(src, ty + 1, c, dva);
            float4 ob = jstep(src, ty + 33, c, dvb);
            oa.x = (rokA && ok0) ? oa.x : 0.f;
            oa.y = (rokA && ok1) ? oa.y : 0.f;
            oa.z = (rokA && ok2) ? oa.z : 0.f;
            oa.w = (rokA && ok3) ? oa.w : 0.f;
            ob.x = (rokB && ok0) ? ob.x : 0.f;
            ob.y = (rokB && ok1) ? ob.y : 0.f;
            ob.z = (rokB && ok2) ? ob.z : 0.f;
            ob.w = (rokB && ok3) ? ob.w : 0.f;
            *(float4*)&dst[(ty + 1) * SSTRIDE + c]  = oa;
            *(float4*)&dst[(ty + 33) * SSTRIDE + c] = ob;
            __syncthreads();
        }
    }
    // after 4 iterations result is in sA

    // ---- store central 56x56 (tile coords [4,60)) ----
    // point A: tile row ty   -> store iff ty >= 4
    // point B: tile row ty+32 -> store iff ty < 28
    if (tx >= 1 && tx < 15) {
        if (ty >= 4) {
            int gy = gyA, gx = gx0;
            if (gy < Hc && gx < Wc)
                *(float4*)&pout[gy * Wc + gx] = *(float4*)&sA[(ty + 1) * SSTRIDE + c];
        }
        if (ty < 28) {
            int gy = gyB, gx = gx0;
            if (gy < Hc && gx < Wc)
                *(float4*)&pout[gy * Wc + gx] = *(float4*)&sA[(ty + 33) * SSTRIDE + c];
        }
    }
}

// ---- pressure gradient ----
__global__ void grad_u_f4_kernel(float* __restrict__ u, const float* __restrict__ p) {
    int qx = blockIdx.x * blockDim.x + threadIdx.x;
    int i  = blockIdx.y * blockDim.y + threadIdx.y + 1;
    int w4 = Wc >> 2;
    if (i > UH - 2 || qx >= w4) return;
    const float4* p4 = (const float4*)p;
    float4 pc = p4[i * w4 + qx];
    float4 pm = p4[(i - 1) * w4 + qx];
    float4* u4 = (float4*)u;
    float4 uu = u4[i * w4 + qx];
    uu.x -= DT * (pc.x - pm.x);
    uu.y -= DT * (pc.y - pm.y);
    uu.z -= DT * (pc.z - pm.z);
    uu.w -= DT * (pc.w - pm.w);
    u4[i * w4 + qx] = uu;
}

__global__ void grad_v_kernel(float* __restrict__ v, const float* __restrict__ p) {
    int j = blockIdx.x * blockDim.x + threadIdx.x + 1;
    int i = blockIdx.y * blockDim.y + threadIdx.y;
    if (i >= VH || j > VW - 2) return;
    v[i * VW + j] -= DT * (p[i * Wc + j] - p[i * Wc + j - 1]);
}

// ---- advects ----
__global__ void advect_u_kernel(const float* __restrict__ u, const float* __restrict__ v,
                                float* __restrict__ out) {
    int j = blockIdx.x * blockDim.x + threadIdx.x;
    int i = blockIdx.y * blockDim.y + threadIdx.y;
    if (i >= UH || j >= UW) return;
    float Y = (float)i, X = (float)j;
    float x_u = fminf(fmaxf(X + 0.5f, 0.0f), (float)(UW - 1));
    float u_i = bilerp(u, UH, UW, Y, x_u);
    float y_v = fminf(fmaxf(Y + 0.5f, 0.0f), (float)(VH - 1));
    float v_i = bilerp(v, VH, VW, y_v, X);
    float px = fminf(fmaxf(X - DT * u_i, 0.0f), (float)(UW - 1));
    float py = fminf(fmaxf(Y - DT * v_i, 0.0f), (float)(UH - 1));
    out[i * UW + j] = bilerp(u, UH, UW, py, px);
}

__global__ void advect_v_kernel(const float* __restrict__ vold, const float* __restrict__ unew,
                                float* __restrict__ out) {
    int j = blockIdx.x * blockDim.x + threadIdx.x;
    int i = blockIdx.y * blockDim.y + threadIdx.y;
    if (i >= VH || j >= VW) return;
    float Y = (float)i, X = (float)j;
    float x_u = fminf(fmaxf(X + 0.5f, 0.0f), (float)(UW - 1));
    float u_i = bilerp(unew, UH, UW, Y, x_u);
    float y_v = fminf(fmaxf(Y + 0.5f, 0.0f), (float)(VH - 1));
    float v_i = bilerp(vold, VH, VW, y_v, X);
    float px = fminf(fmaxf(X - DT * u_i, 0.0f), (float)(VW - 1));
    float py = fminf(fmaxf(Y - DT * v_i, 0.0f), (float)(VH - 1));
    out[i * VW + j] = bilerp(vold, VH, VW, py, px);
}

__global__ void advect_dens_kernel(const float* __restrict__ dens,
                                   const float* __restrict__ unew,
                                   const float* __restrict__ vnew,
                                   float* __restrict__ out) {
    int j = blockIdx.x * blockDim.x + threadIdx.x;
    int i = blockIdx.y * blockDim.y + threadIdx.y;
    if (i >= Hc || j >= Wc) return;
    float Y = (float)i, X = (float)j;
    float x_u = fminf(fmaxf(X + 0.5f, 0.0f), (float)(UW - 1));
    float u_i = bilerp(unew, UH, UW, Y, x_u);
    float y_v = fminf(fmaxf(Y + 0.5f, 0.0f), (float)(VH - 1));
    float v_i = bilerp(vnew, VH, VW, y_v, X);
    float px = fminf(fmaxf(X - DT * u_i, 0.0f), (float)(Wc - 1));
    float py = fminf(fmaxf(Y - DT * v_i, 0.0f), (float)(Hc - 1));
    out[i * Wc + j] = 0.995f * bilerp(dens, Hc, Wc, py, px);
}

extern "C" void kernel_launch(void* const* d_in, const int* in_sizes, int n_in,
                              void* d_out, int out_size) {
    const float* u_in    = (const float*)d_in[0];
    const float* v_in    = (const float*)d_in[1];
    const float* dens_in = (const float*)d_in[2];
    float* out = (float*)d_out;

    float *du, *dv_, *du2, *dv2, *dd, *ddiv, *dp, *dp2;
    cudaGetSymbolAddress((void**)&du,   g_u);
    cudaGetSymbolAddress((void**)&dv_,  g_v);
    cudaGetSymbolAddress((void**)&du2,  g_u2);
    cudaGetSymbolAddress((void**)&dv2,  g_v2);
    cudaGetSymbolAddress((void**)&dd,   g_dens);
    cudaGetSymbolAddress((void**)&ddiv, g_div);
    cudaGetSymbolAddress((void**)&dp,   g_p);
    cudaGetSymbolAddress((void**)&dp2,  g_p2);

    dim3 blkQ(64, 4);
    int w4 = Wc >> 2;
    dim3 grdQ_U((w4 + 63) / 64, (UH + 3) / 4);
    dim3 grdQ_S((w4 + 63) / 64, (Hc + 3) / 4);

    dim3 blkS(128, 2);
    dim3 grdV((VW + 127) / 128, (VH + 1) / 2);
    dim3 grdU((UW + 127) / 128, (UH + 1) / 2);
    dim3 grdS((Wc + 127) / 128, (Hc + 1) / 2);

    // 1. diffuse
    diffuse_f4_kernel<<<grdQ_U, blkQ>>>(u_in, du, UH, UW, DT * VISC);
    diffuse_v_force_kernel<<<grdV, blkS>>>(v_in, dens_in, dv_, DT * VISC);
    diffuse_f4_kernel<<<grdQ_S, blkQ>>>(dens_in, dd, Hc, Wc, DT * VISC * 0.1f);

    // 2. divergence
    div_f4_kernel<<<grdQ_S, blkQ>>>(du, dv_, ddiv);

    // 3. 20 Jacobi iterations = 5 fused x4 launches
    {
        dim3 blkJ(16, 32);
        int gj = (Hc + OT - 1) / OT;   // 37
        dim3 grdJ(gj, gj);
        jacobi4_kernel<<<grdJ, blkJ>>>(dp2, ddiv, dp, 1);   // iters 1-4 (p0=0)
        jacobi4_kernel<<<grdJ, blkJ>>>(dp, ddiv, dp2, 0);   // 5-8
        jacobi4_kernel<<<grdJ, blkJ>>>(dp2, ddiv, dp, 0);   // 9-12
        jacobi4_kernel<<<grdJ, blkJ>>>(dp, ddiv, dp2, 0);   // 13-16
        jacobi4_kernel<<<grdJ, blkJ>>>(dp2, ddiv, dp, 0);   // 17-20 -> dp
    }

    // 4. projection
    {
        dim3 grdGU((w4 + 63) / 64, ((UH - 2) + 3) / 4);
        grad_u_f4_kernel<<<grdGU, blkQ>>>(du, dp);
        dim3 grdGV(((VW - 2) + 127) / 128, (VH + 1) / 2);
        grad_v_kernel<<<grdGV, blkS>>>(dv_, dp);
    }

    // 5. advect
    advect_u_kernel<<<grdU, blkS>>>(du, dv_, du2);
    advect_v_kernel<<<grdV, blkS>>>(dv_, du2, dv2);
    advect_dens_kernel<<<grdS, blkS>>>(dd, du2, dv2, out);
}

// round 5
// speedup vs baseline: 1.9591x; 1.1865x over previous
#include <cuda_runtime.h>

#define Hc 2048
#define Wc 2048
#define UH 2049
#define UW 2048
#define VH 2048
#define VW 2049
#define DT 0.01f
#define VISC 0.001f

// Device scratch
__device__ float g_u  [UH * UW];
__device__ float g_v  [VH * VW];
__device__ float g_u2 [UH * UW];
__device__ float g_v2 [VH * VW];
__device__ float g_dens[Hc * Wc];
__device__ float g_div [Hc * Wc];
__device__ float g_p  [Hc * Wc];
__device__ float g_p2 [Hc * Wc];

__device__ __forceinline__ float bilerp(const float* __restrict__ f, int h, int w,
                                        float y, float x) {
    int x0 = (int)floorf(x);
    int x1 = x0 + 1;
    int y0 = (int)floorf(y);
    int y1 = y0 + 1;
    x0 = min(max(x0, 0), w - 1);
    x1 = min(max(x1, 0), w - 1);
    y0 = min(max(y0, 0), h - 1);
    y1 = min(max(y1, 0), h - 1);
    float x0f = (float)x0, x1f = (float)x1;
    float y0f = (float)y0, y1f = (float)y1;
    float wa = (x1f - x) * (y1f - y);
    float wb = (x - x0f) * (y1f - y);
    float wc = (x1f - x) * (y - y0f);
    float wd = (x - x0f) * (y - y0f);
    return wa * f[y0 * w + x0] + wb * f[y0 * w + x1]
         + wc * f[y1 * w + x0] + wd * f[y1 * w + x1];
}

// ---- diffuse, float4 ----
__global__ void diffuse_f4_kernel(const float* __restrict__ f, float* __restrict__ out,
                                  int h, int w, float a) {
    int qx = blockIdx.x * blockDim.x + threadIdx.x;
    int i  = blockIdx.y * blockDim.y + threadIdx.y;
    int w4 = w >> 2;
    if (i >= h || qx >= w4) return;
    int j0 = qx * 4;
    const float4* f4 = (const float4*)f;
    float4 c  = f4[i * w4 + qx];
    int iu = max(i - 1, 0), id = min(i + 1, h - 1);
    float4 up = f4[iu * w4 + qx];
    float4 dn = f4[id * w4 + qx];
    float lf = (j0 > 0)       ? f[i * w + j0 - 1] : c.x;
    float rt = (j0 + 4 < w)   ? f[i * w + j0 + 4] : c.w;
    float4 r;
    r.x = c.x + a * (up.x + dn.x + lf  + c.y - 4.0f * c.x);
    r.y = c.y + a * (up.y + dn.y + c.x + c.z - 4.0f * c.y);
    r.z = c.z + a * (up.z + dn.z + c.y + c.w - 4.0f * c.z);
    r.w = c.w + a * (up.w + dn.w + c.z + rt  - 4.0f * c.w);
    ((float4*)out)[i * w4 + qx] = r;
}

// ---- diffuse v with force ----
__device__ __forceinline__ float vforce(const float* __restrict__ v,
                                        const float* __restrict__ dens,
                                        int i, int j) {
    float val = v[i * VW + j];
    if (j < Wc) val += (DT * 0.1f) * dens[i * Wc + j];
    return val;
}

__global__ void diffuse_v_force_kernel(const float* __restrict__ v,
                                       const float* __restrict__ dens,
                                       float* __restrict__ out, float a) {
    int j = blockIdx.x * blockDim.x + threadIdx.x;
    int i = blockIdx.y * blockDim.y + threadIdx.y;
    if (i >= VH || j >= VW) return;
    float c  = vforce(v, dens, i, j);
    float up = vforce(v, dens, max(i - 1, 0), j);
    float dn = vforce(v, dens, min(i + 1, VH - 1), j);
    float lf = vforce(v, dens, i, max(j - 1, 0));
    float rt = vforce(v, dens, i, min(j + 1, VW - 1));
    out[i * VW + j] = c + a * (up + dn + lf + rt - 4.0f * c);
}

// ---- divergence ----
__global__ void div_f4_kernel(const float* __restrict__ u, const float* __restrict__ v,
                              float* __restrict__ dv) {
    int qx = blockIdx.x * blockDim.x + threadIdx.x;
    int i  = blockIdx.y * blockDim.y + threadIdx.y;
    int w4 = Wc >> 2;
    if (i >= Hc || qx >= w4) return;
    int j0 = qx * 4;
    const float4* u4 = (const float4*)u;
    float4 u0 = u4[i * w4 + qx];
    float4 u1 = u4[(i + 1) * w4 + qx];
    const float* vr = v + i * VW + j0;
    float v0 = vr[0], v1 = vr[1], v2 = vr[2], v3 = vr[3], v4 = vr[4];
    float4 r;
    r.x = (u1.x - u0.x + v1 - v0) / DT;
    r.y = (u1.y - u0.y + v2 - v1) / DT;
    r.z = (u1.z - u0.z + v3 - v2) / DT;
    r.w = (u1.w - u0.w + v4 - v3) / DT;
    ((float4*)dv)[i * w4 + qx] = r;
}

// ============ fused 4x Jacobi: register strips (2.5D) ============
// Block (16,8) = 128 threads. Each thread: 8-row x 4-col strip in registers.
// Tile 64x64, output 56x56 (halo 4). Vertical exchange of strip boundary rows
// via smem; horizontal via shfl (width 16).
#define OT 56

__device__ __forceinline__ float gload(const float* __restrict__ p, int gy, int gx) {
    return (gy >= 0 && gy < Hc && gx >= 0 && gx < Wc) ? p[gy * Wc + gx] : 0.0f;
}

__global__ void __launch_bounds__(128)
jacobiR_kernel(const float* __restrict__ pin, const float* __restrict__ dv,
               float* __restrict__ pout, int p_zero) {
    __shared__ float4 sTop[8][17];
    __shared__ float4 sBot[8][17];

    const int tx = threadIdx.x;              // 0..15
    const int ty = threadIdx.y;              // 0..7
    const int bx0 = blockIdx.x * OT - 4;
    const int by0 = blockIdx.y * OT - 4;
    const int gx0 = bx0 + tx * 4;
    const int gyBase = by0 + ty * 8;
    const bool border = (blockIdx.x == 0 || blockIdx.y == 0 ||
                         blockIdx.x == gridDim.x - 1 || blockIdx.y == gridDim.y - 1);

    float4 r[8], d[8];

    if (!border) {
        const float4* p4  = (const float4*)pin;
        const float4* dv4 = (const float4*)dv;
        int base = (gyBase * Wc + gx0) >> 2;
        const int rs = Wc >> 2;
        #pragma unroll
        for (int k = 0; k < 8; k++) {
            d[k] = dv4[base + k * rs];
        }
        if (p_zero) {
            float4 z = make_float4(0.f, 0.f, 0.f, 0.f);
            #pragma unroll
            for (int k = 0; k < 8; k++) r[k] = z;
        } else {
            #pragma unroll
            for (int k = 0; k < 8; k++) r[k] = p4[base + k * rs];
        }
    } else {
        #pragma unroll
        for (int k = 0; k < 8; k++) {
            int gy = gyBase + k;
            d[k] = make_float4(gload(dv, gy, gx0),     gload(dv, gy, gx0 + 1),
                               gload(dv, gy, gx0 + 2), gload(dv, gy, gx0 + 3));
            if (p_zero) r[k] = make_float4(0.f, 0.f, 0.f, 0.f);
            else        r[k] = make_float4(gload(pin, gy, gx0),     gload(pin, gy, gx0 + 1),
                                           gload(pin, gy, gx0 + 2), gload(pin, gy, gx0 + 3));
        }
    }

    // domain-interior masks (only used by border blocks)
    bool rok[8];
    bool ok0 = (gx0     >= 1 && gx0     <= Wc - 2);
    bool ok1 = (gx0 + 1 >= 1 && gx0 + 1 <= Wc - 2);
    bool ok2 = (gx0 + 2 >= 1 && gx0 + 2 <= Wc - 2);
    bool ok3 = (gx0 + 3 >= 1 && gx0 + 3 <= Wc - 2);
    #pragma unroll
    for (int k = 0; k < 8; k++)
        rok[k] = (gyBase + k >= 1 && gyBase + k <= Hc - 2);

    const int tyUp = (ty == 0) ? 0 : ty - 1;
    const int tyDn = (ty == 7) ? 7 : ty + 1;

    #pragma unroll
    for (int t = 0; t < 4; t++) {
        sTop[ty][tx] = r[0];
        sBot[ty][tx] = r[7];
        __syncthreads();
        float4 up = sBot[tyUp][tx];
        float4 dn = sTop[tyDn][tx];
        __syncthreads();

        float4 prev = up;
        #pragma unroll
        for (int k = 0; k < 8; k++) {
            float4 ce = r[k];
            float4 below = (k == 7) ? dn : r[k + 1];
            float lf = __shfl_up_sync(0xffffffffu, ce.w, 1, 16);
            float rt = __shfl_down_sync(0xffffffffu, ce.x, 1, 16);
            float4 o;
            o.x = 0.25f * (prev.x + below.x + lf   + ce.y - d[k].x);
            o.y = 0.25f * (prev.y + below.y + ce.x + ce.z - d[k].y);
            o.z = 0.25f * (prev.z + below.z + ce.y + ce.w - d[k].z);
            o.w = 0.25f * (prev.w + below.w + ce.z + rt   - d[k].w);
            if (border) {
                o.x = (rok[k] && ok0) ? o.x : 0.f;
                o.y = (rok[k] && ok1) ? o.y : 0.f;
                o.z = (rok[k] && ok2) ? o.z : 0.f;
                o.w = (rok[k] && ok3) ? o.w : 0.f;
            }
            r[k] = o;
            prev = ce;
        }
    }

    // store central 56x56 (tile rows/cols [4,60))
    if (tx >= 1 && tx < 15 && gx0 < Wc) {
        #pragma unroll
        for (int k = 0; k < 8; k++) {
            int trow = ty * 8 + k;
            if (trow >= 4 && trow < 60) {
                int gy = gyBase + k;
                if (gy < Hc)
                    *(float4*)&pout[gy * Wc + gx0] = r[k];
            }
        }
    }
}

// ---- pressure gradient ----
__global__ void grad_u_f4_kernel(float* __restrict__ u, const float* __restrict__ p) {
    int qx = blockIdx.x * blockDim.x + threadIdx.x;
    int i  = blockIdx.y * blockDim.y + threadIdx.y + 1;
    int w4 = Wc >> 2;
    if (i > UH - 2 || qx >= w4) return;
    const float4* p4 = (const float4*)p;
    float4 pc = p4[i * w4 + qx];
    float4 pm = p4[(i - 1) * w4 + qx];
    float4* u4 = (float4*)u;
    float4 uu = u4[i * w4 + qx];
    uu.x -= DT * (pc.x - pm.x);
    uu.y -= DT * (pc.y - pm.y);
    uu.z -= DT * (pc.z - pm.z);
    uu.w -= DT * (pc.w - pm.w);
    u4[i * w4 + qx] = uu;
}

__global__ void grad_v_kernel(float* __restrict__ v, const float* __restrict__ p) {
    int j = blockIdx.x * blockDim.x + threadIdx.x + 1;
    int i = blockIdx.y * blockDim.y + threadIdx.y;
    if (i >= VH || j > VW - 2) return;
    v[i * VW + j] -= DT * (p[i * Wc + j] - p[i * Wc + j - 1]);
}

// ---- advects ----
__global__ void advect_u_kernel(const float* __restrict__ u, const float* __restrict__ v,
                                float* __restrict__ out) {
    int j = blockIdx.x * blockDim.x + threadIdx.x;
    int i = blockIdx.y * blockDim.y + threadIdx.y;
    if (i >= UH || j >= UW) return;
    float Y = (float)i, X = (float)j;
    float x_u = fminf(fmaxf(X + 0.5f, 0.0f), (float)(UW - 1));
    float u_i = bilerp(u, UH, UW, Y, x_u);
    float y_v = fminf(fmaxf(Y + 0.5f, 0.0f), (float)(VH - 1));
    float v_i = bilerp(v, VH, VW, y_v, X);
    float px = fminf(fmaxf(X - DT * u_i, 0.0f), (float)(UW - 1));
    float py = fminf(fmaxf(Y - DT * v_i, 0.0f), (float)(UH - 1));
    out[i * UW + j] = bilerp(u, UH, UW, py, px);
}

__global__ void advect_v_kernel(const float* __restrict__ vold, const float* __restrict__ unew,
                                float* __restrict__ out) {
    int j = blockIdx.x * blockDim.x + threadIdx.x;
    int i = blockIdx.y * blockDim.y + threadIdx.y;
    if (i >= VH || j >= VW) return;
    float Y = (float)i, X = (float)j;
    float x_u = fminf(fmaxf(X + 0.5f, 0.0f), (float)(UW - 1));
    float u_i = bilerp(unew, UH, UW, Y, x_u);
    float y_v = fminf(fmaxf(Y + 0.5f, 0.0f), (float)(VH - 1));
    float v_i = bilerp(vold, VH, VW, y_v, X);
    float px = fminf(fmaxf(X - DT * u_i, 0.0f), (float)(VW - 1));
    float py = fminf(fmaxf(Y - DT * v_i, 0.0f), (float)(VH - 1));
    out[i * VW + j] = bilerp(vold, VH, VW, py, px);
}

__global__ void advect_dens_kernel(const float* __restrict__ dens,
                                   const float* __restrict__ unew,
                                   const float* __restrict__ vnew,
                                   float* __restrict__ out) {
    int j = blockIdx.x * blockDim.x + threadIdx.x;
    int i = blockIdx.y * blockDim.y + threadIdx.y;
    if (i >= Hc || j >= Wc) return;
    float Y = (float)i, X = (float)j;
    float x_u = fminf(fmaxf(X + 0.5f, 0.0f), (float)(UW - 1));
    float u_i = bilerp(unew, UH, UW, Y, x_u);
    float y_v = fminf(fmaxf(Y + 0.5f, 0.0f), (float)(VH - 1));
    float v_i = bilerp(vnew, VH, VW, y_v, X);
    float px = fminf(fmaxf(X - DT * u_i, 0.0f), (float)(Wc - 1));
    float py = fminf(fmaxf(Y - DT * v_i, 0.0f), (float)(Hc - 1));
    out[i * Wc + j] = 0.995f * bilerp(dens, Hc, Wc, py, px);
}

extern "C" void kernel_launch(void* const* d_in, const int* in_sizes, int n_in,
                              void* d_out, int out_size) {
    const float* u_in    = (const float*)d_in[0];
    const float* v_in    = (const float*)d_in[1];
    const float* dens_in = (const float*)d_in[2];
    float* out = (float*)d_out;

    float *du, *dv_, *du2, *dv2, *dd, *ddiv, *dp, *dp2;
    cudaGetSymbolAddress((void**)&du,   g_u);
    cudaGetSymbolAddress((void**)&dv_,  g_v);
    cudaGetSymbolAddress((void**)&du2,  g_u2);
    cudaGetSymbolAddress((void**)&dv2,  g_v2);
    cudaGetSymbolAddress((void**)&dd,   g_dens);
    cudaGetSymbolAddress((void**)&ddiv, g_div);
    cudaGetSymbolAddress((void**)&dp,   g_p);
    cudaGetSymbolAddress((void**)&dp2,  g_p2);

    dim3 blkQ(64, 4);
    int w4 = Wc >> 2;
    dim3 grdQ_U((w4 + 63) / 64, (UH + 3) / 4);
    dim3 grdQ_S((w4 + 63) / 64, (Hc + 3) / 4);

    dim3 blkS(128, 2);
    dim3 grdV((VW + 127) / 128, (VH + 1) / 2);
    dim3 grdU((UW + 127) / 128, (UH + 1) / 2);
    dim3 grdS((Wc + 127) / 128, (Hc + 1) / 2);

    // 1. diffuse
    diffuse_f4_kernel<<<grdQ_U, blkQ>>>(u_in, du, UH, UW, DT * VISC);
    diffuse_v_force_kernel<<<grdV, blkS>>>(v_in, dens_in, dv_, DT * VISC);
    diffuse_f4_kernel<<<grdQ_S, blkQ>>>(dens_in, dd, Hc, Wc, DT * VISC * 0.1f);

    // 2. divergence
    div_f4_kernel<<<grdQ_S, blkQ>>>(du, dv_, ddiv);

    // 3. 20 Jacobi iterations = 5 fused x4 launches (register strips)
    {
        dim3 blkJ(16, 8);
        int gj = (Hc + OT - 1) / OT;   // 37
        dim3 grdJ(gj, gj);
        jacobiR_kernel<<<grdJ, blkJ>>>(dp2, ddiv, dp, 1);   // iters 1-4 (p0=0)
        jacobiR_kernel<<<grdJ, blkJ>>>(dp, ddiv, dp2, 0);   // 5-8
        jacobiR_kernel<<<grdJ, blkJ>>>(dp2, ddiv, dp, 0);   // 9-12
        jacobiR_kernel<<<grdJ, blkJ>>>(dp, ddiv, dp2, 0);   // 13-16
        jacobiR_kernel<<<grdJ, blkJ>>>(dp2, ddiv, dp, 0);   // 17-20 -> dp
    }

    // 4. projection
    {
        dim3 grdGU((w4 + 63) / 64, ((UH - 2) + 3) / 4);
        grad_u_f4_kernel<<<grdGU, blkQ>>>(du, dp);
        dim3 grdGV(((VW - 2) + 127) / 128, (VH + 1) / 2);
        grad_v_kernel<<<grdGV, blkS>>>(dv_, dp);
    }

    // 5. advect
    advect_u_kernel<<<grdU, blkS>>>(du, dv_, du2);
    advect_v_kernel<<<grdV, blkS>>>(dv_, du2, dv2);
    advect_dens_kernel<<<grdS, blkS>>>(dd, du2, dv2, out);
}